// round 14
// baseline (speedup 1.0000x reference)
#include <cuda_runtime.h>
#include <cstdint>

#define BATCH   8192
#define BOX     10
#define PAIR    90                  // BOX*(BOX-1)
#define NUM_OT  151
#define NUM_QT  65
#define SLICE   (NUM_OT * NUM_OT)   // 22801 floats per (qt, pair) slice
#define NSLICE  (NUM_QT * PAIR)     // 5850
#define MAXB    512                 // cap on batches per qus_type (mean 126)

#define NCHUNK     4
#define CHUNK_SL   ((NSLICE + NCHUNK - 1) / NCHUNK)   // 1463 slices (~133MB)
#define SCAT_BLKS  128
#define COPY_BLKS  1184
#define GRID       (SCAT_BLKS + COPY_BLKS)

// ---------------- device scratch (static, no allocation) -------------------
__device__ int                g_count[NUM_QT];
// entries[qt][slot][p] : packed {off = ol1*151+ol2 : u32, val : f32}
__device__ unsigned long long g_entries[(size_t)NUM_QT * MAXB * PAIR];  // 24 MB

// ---------------------------------------------------------------------------
// Chunk kernel.
//   blocks [0, SCAT_BLKS):   either entries-precompute (kernel 0) or
//                            scatter for the previously-copied chunk
//                            (L2-hot lines; runs first in dispatch order).
//   blocks [SCAT_BLKS, ...): PURE streaming copy of this chunk
//                            (3-instr inner loop, .cs loads, WB stores).
// Cross-chunk ordering comes free from stream-ordered launches: no flags,
// no fences, no spinning.
// ---------------------------------------------------------------------------
__global__ void __launch_bounds__(256)
chunk_kernel(const int*   __restrict__ obj_label,   // [BATCH, BOX]
             const int*   __restrict__ qus_type,    // [BATCH]
             const float* __restrict__ attention,   // [BATCH, BOX]
             const float* __restrict__ src,         // [65,90,151,151]
             float*       __restrict__ out,
             int copy_lo, int copy_hi,              // slice range to copy
             int scat_lo, int scat_hi,              // slice range to scatter
             int do_entries)                        // kernel 0: precompute
{
    if (blockIdx.x < SCAT_BLKS) {
        if (do_entries) {
            // ---- entries precompute, hidden under chunk-0's copy ----
            int b = blockIdx.x * 256 + threadIdx.x;
            if (b < BATCH) {
                int qt   = __ldg(qus_type + b);
                int slot = atomicAdd(&g_count[qt], 1);
                if (slot < MAXB) {
                    int   lab[BOX];
                    float att[BOX];
                    #pragma unroll
                    for (int k = 0; k < BOX; k++) {
                        lab[k] = __ldg(obj_label + b * BOX + k);
                        att[k] = __ldg(attention + b * BOX + k);
                    }
                    unsigned long long* dst =
                        g_entries + ((size_t)qt * MAXB + slot) * PAIR;
                    #pragma unroll
                    for (int i = 0; i < BOX; i++) {
                        #pragma unroll
                        for (int jj = 0; jj < BOX - 1; jj++) {
                            int j = jj + (jj >= i ? 1 : 0);   // all j != i
                            unsigned int off = (unsigned)(lab[j] * NUM_OT + lab[i]);
                            float        val = att[j] * att[i];
                            dst[i * (BOX - 1) + jj] =
                                ((unsigned long long)off << 32) |
                                (unsigned long long)__float_as_uint(val);
                        }
                    }
                }
            }
        } else {
            // ---- scatter for the chunk copied by the PREVIOUS launch ----
            for (int t = scat_lo + (int)blockIdx.x; t < scat_hi; t += SCAT_BLKS) {
                int qt = t / PAIR;
                int p  = t - qt * PAIR;
                int cnt = g_count[qt];
                if (cnt > MAXB) cnt = MAXB;

                float* d = out + (size_t)t * SLICE;
                const unsigned long long* __restrict__ ent =
                    g_entries + (size_t)qt * MAXB * PAIR + (size_t)p;

                for (int k = threadIdx.x; k < cnt; k += 256) {
                    unsigned long long e = __ldg(ent + (size_t)k * PAIR);
                    atomicAdd(d + (unsigned)(e >> 32),
                              __uint_as_float((unsigned)e));
                }
            }
        }
        return;
    }

    // ---- pure streaming copy of [copy_lo, copy_hi) slices ----
    if (copy_lo >= copy_hi) return;

    const size_t f0 = (size_t)copy_lo * SLICE;
    const size_t f1 = (size_t)copy_hi * SLICE;
    const float* s = src + f0;
    float*       d = out + f0;
    const long long len = (long long)(f1 - f0);

    const int cb = (int)blockIdx.x - SCAT_BLKS;
    const int head = (4 - (int)(f0 & 3)) & 3;
    if (cb == 0 && threadIdx.x < (unsigned)head)
        d[threadIdx.x] = __ldcs(s + threadIdx.x);

    const long long n4 = (len - head) >> 2;
    const float4* __restrict__ s4 = (const float4*)(s + head);
    float4*       __restrict__ d4 = (float4*)(d + head);
    const long long stride = (long long)COPY_BLKS * 256;
    #pragma unroll 4
    for (long long i = (long long)cb * 256 + threadIdx.x; i < n4; i += stride)
        d4[i] = __ldcs(s4 + i);              // WB store: lingers in L2

    const long long ts = head + (n4 << 2);
    const int tail = (int)(len - ts);        // 0..3
    if (cb == 0 && threadIdx.x < (unsigned)tail)
        d[ts + threadIdx.x] = __ldcs(s + ts + threadIdx.x);
}

// ---------------------------------------------------------------------------
// Launch: memset(counters) -> chunk kernels (copy c | scatter c-1), all on
// one stream, all graph-capturable.
// ---------------------------------------------------------------------------
extern "C" void kernel_launch(void* const* d_in, const int* in_sizes, int n_in,
                              void* d_out, int out_size)
{
    const int*   obj_label    = (const int*)  d_in[0]; // [8192,10] int32
    const int*   qus_type     = (const int*)  d_in[1]; // [8192]    int32
    const float* attention    = (const float*)d_in[2]; // [8192,10] float32
    const float* score_matrix = (const float*)d_in[3]; // [65,90,151,151] float32
    float*       out          = (float*)d_out;

    static int* d_count = nullptr;
    if (!d_count)
        cudaGetSymbolAddress((void**)&d_count, g_count);

    cudaMemsetAsync(d_count, 0, NUM_QT * sizeof(int), 0);

    for (int c = 0; c <= NCHUNK; c++) {
        int copy_lo = c * CHUNK_SL;          if (copy_lo > NSLICE) copy_lo = NSLICE;
        int copy_hi = copy_lo + CHUNK_SL;    if (copy_hi > NSLICE) copy_hi = NSLICE;
        int scat_lo = (c - 1) * CHUNK_SL;    if (scat_lo < 0) scat_lo = 0;
        int scat_hi = c * CHUNK_SL;          if (scat_hi > NSLICE) scat_hi = NSLICE;
        if (c == 0) { scat_lo = scat_hi = 0; }

        chunk_kernel<<<GRID, 256>>>(obj_label, qus_type, attention,
                                    score_matrix, out,
                                    copy_lo, copy_hi,
                                    scat_lo, scat_hi,
                                    c == 0 ? 1 : 0);
    }
}